// round 6
// baseline (speedup 1.0000x reference)
#include <cuda_runtime.h>
#include <math.h>

#define D_MODEL 1024
#define N_HEADS 16
#define DH      64
#define BATCH   2
#define SEQ     2048
#define BT      (BATCH * SEQ)      // 4096
#define D3      (3 * D_MODEL)      // 3072

// ---------------- scratch (device globals; no allocation allowed) ----------
__device__ float g_qkv[(size_t)3 * BT * D_MODEL];     // [3][B*H][T][DH]
__device__ float g_attn[(size_t)BT * D_MODEL];        // [B,T,D]

// ---------------- helpers ----------------------------------------------------
__device__ __forceinline__ unsigned f2tf32(float f) {
    unsigned r;
    asm("cvt.rna.tf32.f32 %0, %1;" : "=r"(r) : "f"(f));
    return r;
}

__device__ __forceinline__ void mma_tf32(
    float& c0, float& c1, float& c2, float& c3,
    unsigned a0, unsigned a1, unsigned a2, unsigned a3,
    unsigned b0, unsigned b1) {
    asm volatile(
        "mma.sync.aligned.m16n8k8.row.col.f32.tf32.tf32.f32 "
        "{%0,%1,%2,%3}, {%4,%5,%6,%7}, {%8,%9}, {%0,%1,%2,%3};"
        : "+f"(c0), "+f"(c1), "+f"(c2), "+f"(c3)
        : "r"(a0), "r"(a1), "r"(a2), "r"(a3), "r"(b0), "r"(b1));
}

// ldmatrix x4: four 8x(4x32b) subtiles; lane l supplies the row address for
// subtile l>>3, row l&7. Delivers reg r_s to lane t as element (t/4, t%4).
__device__ __forceinline__ void ldsm_x4(
    unsigned& r0, unsigned& r1, unsigned& r2, unsigned& r3, unsigned addr) {
    asm volatile("ldmatrix.sync.aligned.m8n8.x4.shared.b16 {%0,%1,%2,%3}, [%4];"
                 : "=r"(r0), "=r"(r1), "=r"(r2), "=r"(r3) : "r"(addr));
}

__device__ __forceinline__ unsigned smem_u32_of(const void* p) {
    unsigned r;
    asm("{ .reg .u64 t; cvta.to.shared.u64 t, %1; cvt.u32.u64 %0, t; }"
        : "=r"(r) : "l"(p));
    return r;
}

// ---------------- TF32 GEMM: C[M,N] = A[M,K] @ W[N,K]^T ----------------------
// Block 128x128, k-step 32, cp.async 2-stage double buffer, in-place tf32
// convert pass per k-step, ldmatrix fragment loads.
#define KSTEP 32
#define SPAD  36
#define STAGE_FLOATS (2 * 128 * SPAD)                  // A + B per stage
#define STAGE_BYTES  (STAGE_FLOATS * 4)
#define GEMM_SMEM_BYTES (2 * STAGE_BYTES)               // 73728

template <int MODE>
__global__ __launch_bounds__(256, 2) void gemm_tf32_kernel(
    const float* __restrict__ A, const float* __restrict__ W,
    float* __restrict__ C, int M, int N, int K) {
    extern __shared__ float smem[];
    const unsigned smem_u32 = smem_u32_of(smem);

    const int tid  = threadIdx.x;
    const int lane = tid & 31;
    const int wid  = tid >> 5;
    const int warp_m = wid & 3;
    const int warp_n = wid >> 2;
    const int bm = blockIdx.y * 128;
    const int bn = blockIdx.x * 128;
    const int lr = lane >> 2;
    const int lc = lane & 3;

    // copy mapping: thread handles rows c_row+32*it (it=0..3), 16B at col c_col
    const int c_row = tid >> 3;        // 0..31
    const int c_col = (tid & 7) * 4;   // 0..28
    const float* Abase = A + (size_t)(bm + c_row) * K + c_col;
    const float* Wbase = W + (size_t)(bn + c_row) * K + c_col;

    // ldmatrix lane offsets (bytes within a stage)
    const int ls  = lane >> 3;          // subtile 0..3
    const int rin = lane & 7;
    const int fr  = ((ls & 1) << 3) + rin;   // +8 rows for odd subtile
    const int fc  = (ls >> 1) * 4;           // +4 cols for subtiles 2,3
    const unsigned a_off0 = (unsigned)(((warp_m * 32 + fr) * SPAD + fc) * 4);
    const unsigned a_off1 = (unsigned)(((warp_m * 32 + 16 + fr) * SPAD + fc) * 4);
    unsigned b_off[4];
    #pragma unroll
    for (int jj = 0; jj < 4; jj++)
        b_off[jj] = (unsigned)((128 * SPAD + (warp_n * 64 + jj * 16 + fr) * SPAD + fc) * 4);

#define COPY_TILE(k0, s) {                                                     \
        unsigned base_ = smem_u32 + (unsigned)((s) * STAGE_BYTES);             \
        _Pragma("unroll")                                                      \
        for (int it = 0; it < 4; it++) {                                       \
            int row_ = c_row + 32 * it;                                        \
            unsigned da_ = base_ + (unsigned)((row_ * SPAD + c_col) * 4);      \
            const float* sa_ = Abase + (size_t)(32 * it) * K + (k0);           \
            asm volatile("cp.async.cg.shared.global [%0], [%1], 16;"           \
                         :: "r"(da_), "l"(sa_));                               \
            unsigned db_ = base_ +                                             \
                (unsigned)((128 * SPAD + row_ * SPAD + c_col) * 4);            \
            const float* sb_ = Wbase + (size_t)(32 * it) * K + (k0);           \
            asm volatile("cp.async.cg.shared.global [%0], [%1], 16;"           \
                         :: "r"(db_), "l"(sb_));                               \
        }                                                                      \
        asm volatile("cp.async.commit_group;"); }

    float acc[2][8][4];
    #pragma unroll
    for (int i = 0; i < 2; i++)
        #pragma unroll
        for (int j = 0; j < 8; j++)
            #pragma unroll
            for (int c = 0; c < 4; c++) acc[i][j][c] = 0.f;

    COPY_TILE(0, 0);

    const int nk = K / KSTEP;
    for (int i = 0; i < nk; i++) {
        asm volatile("cp.async.wait_group 0;");
        __syncthreads();

        // in-place fp32 -> tf32 convert of own chunks
        float* stage = smem + (size_t)(i & 1) * STAGE_FLOATS;
        #pragma unroll
        for (int it = 0; it < 4; it++) {
            int off = (c_row + 32 * it) * SPAD + c_col;
            float4 va = *(float4*)&stage[off];
            *(uint4*)&stage[off] =
                make_uint4(f2tf32(va.x), f2tf32(va.y), f2tf32(va.z), f2tf32(va.w));
            float4 vb = *(float4*)&stage[128 * SPAD + off];
            *(uint4*)&stage[128 * SPAD + off] =
                make_uint4(f2tf32(vb.x), f2tf32(vb.y), f2tf32(vb.z), f2tf32(vb.w));
        }
        __syncthreads();

        if (i + 1 < nk) COPY_TILE((i + 1) * KSTEP, (i + 1) & 1);

        const unsigned sbase = smem_u32 + (unsigned)((i & 1) * STAGE_BYTES);
        #pragma unroll
        for (int kk = 0; kk < KSTEP; kk += 8) {
            unsigned a[2][4];
            ldsm_x4(a[0][0], a[0][1], a[0][2], a[0][3], sbase + a_off0 + kk * 4);
            ldsm_x4(a[1][0], a[1][1], a[1][2], a[1][3], sbase + a_off1 + kk * 4);
            #pragma unroll
            for (int jj = 0; jj < 4; jj++) {
                unsigned b0a, b0b, b1a, b1b;
                ldsm_x4(b0a, b0b, b1a, b1b, sbase + b_off[jj] + kk * 4);
                int j0 = 2 * jj, j1 = 2 * jj + 1;
                mma_tf32(acc[0][j0][0], acc[0][j0][1], acc[0][j0][2], acc[0][j0][3],
                         a[0][0], a[0][1], a[0][2], a[0][3], b0a, b1a);
                mma_tf32(acc[1][j0][0], acc[1][j0][1], acc[1][j0][2], acc[1][j0][3],
                         a[1][0], a[1][1], a[1][2], a[1][3], b0a, b1a);
                mma_tf32(acc[0][j1][0], acc[0][j1][1], acc[0][j1][2], acc[0][j1][3],
                         a[0][0], a[0][1], a[0][2], a[0][3], b0b, b1b);
                mma_tf32(acc[1][j1][0], acc[1][j1][1], acc[1][j1][2], acc[1][j1][3],
                         a[1][0], a[1][1], a[1][2], a[1][3], b0b, b1b);
            }
        }
    }
#undef COPY_TILE

    #pragma unroll
    for (int i = 0; i < 2; i++) {
        #pragma unroll
        for (int j = 0; j < 8; j++) {
            #pragma unroll
            for (int c = 0; c < 4; c++) {
                int m = bm + warp_m * 32 + i * 16 + lr + ((c >= 2) ? 8 : 0);
                int n = bn + warp_n * 64 + j * 8 + 2 * lc + (c & 1);
                if (MODE == 0) {
                    int b = m >> 11;
                    int t = m & (SEQ - 1);
                    int which = n >> 10;
                    int d = n & (D_MODEL - 1);
                    int h = d >> 6;
                    int hd = d & 63;
                    size_t dst = (size_t)which * ((size_t)BT * D_MODEL) +
                                 (((size_t)(b * N_HEADS + h) * SEQ + t) << 6) + hd;
                    C[dst] = acc[i][j][c];
                } else {
                    C[(size_t)m * N + n] = acc[i][j][c];
                }
            }
        }
    }
}

// ---------------- TF32 tensor-core causal flash attention --------------------
// Block: 128 Q rows, 8 warps (16 rows each). K/V tiles 64x64 in SMEM.
// K fragments via ldmatrix; V via plain LDS.
#define QT 128
#define KT 64
#define KS_PAD 68
#define VS_PAD 72

__global__ __launch_bounds__(256) void attn_mma_kernel(
    const float* __restrict__ qkv, float* __restrict__ out) {
    __shared__ __align__(16) unsigned Ks[KT][KS_PAD];
    __shared__ __align__(16) unsigned Vs[KT][VS_PAD];

    const int tid  = threadIdx.x;
    const int lane = tid & 31;
    const int wid  = tid >> 5;
    const int lr = lane >> 2;
    const int lc = lane & 3;

    const int bh = blockIdx.y;
    const int qt = (gridDim.x - 1) - blockIdx.x;   // heavy tiles first
    const int q0 = qt * QT;

    const float* Qp = qkv + ((size_t)bh * SEQ + q0) * DH;
    const float* Kp = qkv + (size_t)BT * D_MODEL + (size_t)bh * SEQ * DH;
    const float* Vp = qkv + (size_t)2 * BT * D_MODEL + (size_t)bh * SEQ * DH;

    // ldmatrix lane offsets into Ks (bytes)
    const unsigned ks_u32 = smem_u32_of(&Ks[0][0]);
    const int ls  = lane >> 3;
    const int rin = lane & 7;
    const int fr  = ((ls & 1) << 3) + rin;
    const int fc  = (ls >> 1) * 4;
    unsigned k_off[4];
    #pragma unroll
    for (int jj = 0; jj < 4; jj++)
        k_off[jj] = (unsigned)(((jj * 16 + fr) * KS_PAD + fc) * 4);

    unsigned qa[8][4];
    {
        const int r0 = wid * 16 + lr;
        #pragma unroll
        for (int kk = 0; kk < 8; kk++) {
            int c = kk * 8 + lc;
            qa[kk][0] = f2tf32(0.125f * Qp[(size_t)r0 * DH + c]);
            qa[kk][1] = f2tf32(0.125f * Qp[(size_t)(r0 + 8) * DH + c]);
            qa[kk][2] = f2tf32(0.125f * Qp[(size_t)r0 * DH + c + 4]);
            qa[kk][3] = f2tf32(0.125f * Qp[(size_t)(r0 + 8) * DH + c + 4]);
        }
    }

    float o[8][4];
    #pragma unroll
    for (int n = 0; n < 8; n++)
        #pragma unroll
        for (int c = 0; c < 4; c++) o[n][c] = 0.f;
    float m0 = -1e30f, m1 = -1e30f, l0 = 0.f, l1 = 0.f;

    const int nkt = 2 * qt + 2;
    const int row0 = q0 + wid * 16 + lr;
    const int row1 = row0 + 8;

    for (int kt = 0; kt < nkt; kt++) {
        const int k0 = kt * KT;
        __syncthreads();
        #pragma unroll
        for (int it = 0; it < 4; it++) {
            int i = tid + 256 * it;
            int r = i >> 4;
            int c = (i & 15) * 4;
            float4 kv = *(const float4*)&Kp[(size_t)(k0 + r) * DH + c];
            *(uint4*)&Ks[r][c] = make_uint4(f2tf32(kv.x), f2tf32(kv.y),
                                            f2tf32(kv.z), f2tf32(kv.w));
            float4 vv = *(const float4*)&Vp[(size_t)(k0 + r) * DH + c];
            *(uint4*)&Vs[r][c] = make_uint4(f2tf32(vv.x), f2tf32(vv.y),
                                            f2tf32(vv.z), f2tf32(vv.w));
        }
        __syncthreads();

        // ---- S = (Q/8) @ K^T via ldmatrix B fragments ----
        float s[8][4];
        #pragma unroll
        for (int n = 0; n < 8; n++)
            #pragma unroll
            for (int c = 0; c < 4; c++) s[n][c] = 0.f;

        #pragma unroll
        for (int kk = 0; kk < 8; kk++) {
            #pragma unroll
            for (int jj = 0; jj < 4; jj++) {
                unsigned b0a, b0b, b1a, b1b;
                ldsm_x4(b0a, b0b, b1a, b1b, ks_u32 + k_off[jj] + kk * 32);
                int n0 = 2 * jj, n1 = 2 * jj + 1;
                mma_tf32(s[n0][0], s[n0][1], s[n0][2], s[n0][3],
                         qa[kk][0], qa[kk][1], qa[kk][2], qa[kk][3], b0a, b1a);
                mma_tf32(s[n1][0], s[n1][1], s[n1][2], s[n1][3],
                         qa[kk][0], qa[kk][1], qa[kk][2], qa[kk][3], b0b, b1b);
            }
        }

        if (kt >= 2 * qt) {
            #pragma unroll
            for (int n = 0; n < 8; n++) {
                int col0 = k0 + n * 8 + 2 * lc;
                if (col0 > row0)     s[n][0] = -1e30f;
                if (col0 + 1 > row0) s[n][1] = -1e30f;
                if (col0 > row1)     s[n][2] = -1e30f;
                if (col0 + 1 > row1) s[n][3] = -1e30f;
            }
        }

        float mx0 = -1e30f, mx1 = -1e30f;
        #pragma unroll
        for (int n = 0; n < 8; n++) {
            mx0 = fmaxf(mx0, fmaxf(s[n][0], s[n][1]));
            mx1 = fmaxf(mx1, fmaxf(s[n][2], s[n][3]));
        }
        mx0 = fmaxf(mx0, __shfl_xor_sync(0xffffffffu, mx0, 1));
        mx0 = fmaxf(mx0, __shfl_xor_sync(0xffffffffu, mx0, 2));
        mx1 = fmaxf(mx1, __shfl_xor_sync(0xffffffffu, mx1, 1));
        mx1 = fmaxf(mx1, __shfl_xor_sync(0xffffffffu, mx1, 2));

        float mn0 = fmaxf(m0, mx0), mn1 = fmaxf(m1, mx1);
        float alpha0 = __expf(m0 - mn0), alpha1 = __expf(m1 - mn1);
        m0 = mn0; m1 = mn1;

        float sum0 = 0.f, sum1 = 0.f;
        #pragma unroll
        for (int n = 0; n < 8; n++) {
            s[n][0] = __expf(s[n][0] - mn0);
            s[n][1] = __expf(s[n][1] - mn0);
            s[n][2] = __expf(s[n][2] - mn1);
            s[n][3] = __expf(s[n][3] - mn1);
            sum0 += s[n][0] + s[n][1];
            sum1 += s[n][2] + s[n][3];
        }
        sum0 += __shfl_xor_sync(0xffffffffu, sum0, 1);
        sum0 += __shfl_xor_sync(0xffffffffu, sum0, 2);
        sum1 += __shfl_xor_sync(0xffffffffu, sum1, 1);
        sum1 += __shfl_xor_sync(0xffffffffu, sum1, 2);
        l0 = l0 * alpha0 + sum0;
        l1 = l1 * alpha1 + sum1;

        #pragma unroll
        for (int n = 0; n < 8; n++) {
            o[n][0] *= alpha0; o[n][1] *= alpha0;
            o[n][2] *= alpha1; o[n][3] *= alpha1;
        }

        const int qbase = lane & ~3;
        const int h0 = qbase + (lc >> 1);
        const int h1 = h0 + 2;
        const bool odd = lc & 1;
        #pragma unroll
        for (int n = 0; n < 8; n++) {
            float t0 = __shfl_sync(0xffffffffu, s[n][0], h0);
            float t1 = __shfl_sync(0xffffffffu, s[n][1], h0);
            float u0 = __shfl_sync(0xffffffffu, s[n][0], h1);
            float u1 = __shfl_sync(0xffffffffu, s[n][1], h1);
            float v0 = __shfl_sync(0xffffffffu, s[n][2], h0);
            float v1 = __shfl_sync(0xffffffffu, s[n][3], h0);
            float w0 = __shfl_sync(0xffffffffu, s[n][2], h1);
            float w1 = __shfl_sync(0xffffffffu, s[n][3], h1);
            s[n][0] = __uint_as_float(f2tf32(odd ? t1 : t0));
            s[n][1] = __uint_as_float(f2tf32(odd ? v1 : v0));
            s[n][2] = __uint_as_float(f2tf32(odd ? u1 : u0));
            s[n][3] = __uint_as_float(f2tf32(odd ? w1 : w0));
        }

        #pragma unroll
        for (int d = 0; d < 8; d++) {
            #pragma unroll
            for (int kk = 0; kk < 8; kk++) {
                unsigned b0 = Vs[kk * 8 + lc][d * 8 + lr];
                unsigned b1 = Vs[kk * 8 + lc + 4][d * 8 + lr];
                mma_tf32(o[d][0], o[d][1], o[d][2], o[d][3],
                         __float_as_uint(s[kk][0]), __float_as_uint(s[kk][1]),
                         __float_as_uint(s[kk][2]), __float_as_uint(s[kk][3]),
                         b0, b1);
            }
        }
    }

    const int b = bh >> 4;
    const int h = bh & 15;
    const float inv0 = 1.f / l0;
    const float inv1 = 1.f / l1;
    #pragma unroll
    for (int n = 0; n < 8; n++) {
        int d = h * DH + n * 8 + 2 * lc;
        float2 r0v = make_float2(o[n][0] * inv0, o[n][1] * inv0);
        float2 r1v = make_float2(o[n][2] * inv1, o[n][3] * inv1);
        *(float2*)&out[((size_t)(b * SEQ + row0)) * D_MODEL + d] = r0v;
        *(float2*)&out[((size_t)(b * SEQ + row1)) * D_MODEL + d] = r1v;
    }
}

// ---------------- launch ------------------------------------------------------
extern "C" void kernel_launch(void* const* d_in, const int* in_sizes, int n_in,
                              void* d_out, int out_size) {
    const float* x     = (const float*)d_in[0];
    const float* W_in  = (const float*)d_in[1];
    const float* W_out = (const float*)d_in[2];
    float* out = (float*)d_out;

    float *qkv, *attn;
    cudaGetSymbolAddress((void**)&qkv,  g_qkv);
    cudaGetSymbolAddress((void**)&attn, g_attn);

    cudaFuncSetAttribute(gemm_tf32_kernel<0>,
                         cudaFuncAttributeMaxDynamicSharedMemorySize, GEMM_SMEM_BYTES);
    cudaFuncSetAttribute(gemm_tf32_kernel<1>,
                         cudaFuncAttributeMaxDynamicSharedMemorySize, GEMM_SMEM_BYTES);

    // 1. QKV projection (TF32 mma + cp.async + ldmatrix)
    {
        dim3 grid(D3 / 128, BT / 128);
        gemm_tf32_kernel<0><<<grid, 256, GEMM_SMEM_BYTES>>>(x, W_in, qkv, BT, D3, D_MODEL);
    }

    // 2. causal flash attention (TF32 mma + ldmatrix K) -> g_attn [B,T,D]
    {
        dim3 grid(SEQ / QT, BATCH * N_HEADS);  // (16, 32)
        attn_mma_kernel<<<grid, 256>>>(qkv, attn);
    }

    // 3. output projection (TF32 mma + cp.async + ldmatrix) -> d_out
    {
        dim3 grid(D_MODEL / 128, BT / 128);
        gemm_tf32_kernel<1><<<grid, 256, GEMM_SMEM_BYTES>>>(attn, W_out, out, BT, D_MODEL, D_MODEL);
    }
}